// round 8
// baseline (speedup 1.0000x reference)
#include <cuda_runtime.h>
#include <cuda_bf16.h>
#include <cstdint>
#include <math.h>

// Problem constants
#define B_    2
#define N_    4096
#define D_    1024
#define HQ_   16
#define HKV_  4
#define HD_   64
#define ROWS_ (B_*N_)      // 8192

// ---------------------------------------------------------------------------
// Scratch (device globals; no runtime allocation)
// ---------------------------------------------------------------------------
__device__ float g_Q[(size_t)B_*HQ_*N_*HD_];   // [B,HQ,N,HD]  fp32
__device__ float g_K[(size_t)B_*HKV_*N_*HD_];  // [B,HKV,N,HD] fp32
__device__ float g_V[(size_t)B_*HKV_*N_*HD_];  // [B,HKV,N,HD] fp32
__device__ float g_O[(size_t)B_*N_*HQ_*HD_];   // [B,N,HQ,HD]  fp32

// bf16 hi/lo images for attention operands
__device__ uint16_t g_Kh[(size_t)8*N_*HD_],  g_Kl[(size_t)8*N_*HD_];   // [bkv][key][dim]
__device__ uint16_t g_Vth[(size_t)8*HD_*N_], g_Vtl[(size_t)8*HD_*N_];  // [bkv][dim][key]

// bf16 hi/lo images for projection GEMMs
__device__ uint16_t g_xh[(size_t)ROWS_*D_],  g_xl[(size_t)ROWS_*D_];   // x row-major
__device__ uint16_t g_Wth[(size_t)1536*D_],  g_Wtl[(size_t)1536*D_];   // [Wq|Wk|Wv]^T [n][k]
__device__ uint16_t g_Woth[(size_t)D_*D_],   g_Wotl[(size_t)D_*D_];    // Wo^T [n][k]
__device__ uint16_t g_Oh[(size_t)ROWS_*D_],  g_Ol[(size_t)ROWS_*D_];   // attn out row-major

// ---------------------------------------------------------------------------
// Helpers
// ---------------------------------------------------------------------------
// pack (f0,f1) -> bf16x2 hi (low half = f0), plus residual lo pair
__device__ __forceinline__ void split2(float f0, float f1, uint32_t& hi, uint32_t& lo) {
    uint32_t h;
    asm("cvt.rn.bf16x2.f32 %0, %1, %2;" : "=r"(h) : "f"(f1), "f"(f0));
    float h0 = __uint_as_float(h << 16);
    float h1 = __uint_as_float(h & 0xffff0000u);
    float r0 = f0 - h0, r1 = f1 - h1;
    uint32_t l_;
    asm("cvt.rn.bf16x2.f32 %0, %1, %2;" : "=r"(l_) : "f"(r1), "f"(r0));
    hi = h; lo = l_;
}

// warp mma: D(16x8,f32) += A(16x16 bf16 row-major) * B(16x8 bf16 col-major)
__device__ __forceinline__ void mma16816(float* d, const uint32_t* a, uint32_t b0, uint32_t b1) {
    asm volatile(
        "mma.sync.aligned.m16n8k16.row.col.f32.bf16.bf16.f32 "
        "{%0,%1,%2,%3}, {%4,%5,%6,%7}, {%8,%9}, {%0,%1,%2,%3};"
        : "+f"(d[0]), "+f"(d[1]), "+f"(d[2]), "+f"(d[3])
        : "r"(a[0]), "r"(a[1]), "r"(a[2]), "r"(a[3]), "r"(b0), "r"(b1));
}

// ---------------------------------------------------------------------------
// convert_pairs: fp32 buffer -> hi/lo bf16 images (pairwise).
// mode 0: src (kernel arg) -> g_xh/g_xl.  mode 1: g_O -> g_Oh/g_Ol.
// (pointers to __device__ globals resolved IN DEVICE CODE — host-side
//  addresses of __device__ symbols are invalid.)
// ---------------------------------------------------------------------------
__global__ void convert_pairs(const float* src, int mode)
{
    size_t i = (size_t)blockIdx.x * blockDim.x + threadIdx.x;  // pair index
    const float* s = mode ? g_O : src;
    uint16_t* dh = mode ? g_Oh : g_xh;
    uint16_t* dl = mode ? g_Ol : g_xl;
    float2 v = ((const float2*)s)[i];
    uint32_t hi, lo;
    split2(v.x, v.y, hi, lo);
    ((uint32_t*)dh)[i] = hi;
    ((uint32_t*)dl)[i] = lo;
}

// ---------------------------------------------------------------------------
// convert_wt: W [k][n] (ldn wide) -> W^T hi/lo [noff + n][1024]
// wsel 0 -> g_Wth/g_Wtl, wsel 1 -> g_Woth/g_Wotl (resolved in device code).
// grid (8 k-tiles of 128, ldn/64), block 128. (structure = verified convert_vt)
// ---------------------------------------------------------------------------
__global__ void convert_wt(const float* __restrict__ src, int ldn, int noff, int wsel)
{
    __shared__ float sm[128*68];
    uint16_t* dh = wsel ? g_Woth : g_Wth;
    uint16_t* dl = wsel ? g_Wotl : g_Wtl;
    int t = blockIdx.x;       // k tile of 128
    int nb = blockIdx.y;      // n chunk of 64
    int tid = threadIdx.x;
    const float* s = src + (size_t)(t*128 + tid) * ldn + nb*64;
    #pragma unroll
    for (int u = 0; u < 16; u++)
        *(float4*)&sm[tid*68 + u*4] = *(const float4*)(s + u*4);
    __syncthreads();
    int d = tid >> 1, half = tid & 1;
    size_t rowbase = (size_t)(noff + nb*64 + d) * 1024;
    #pragma unroll
    for (int j = 0; j < 32; j++) {
        int k2 = half*64 + 2*j;
        float f0 = sm[k2*68 + d];
        float f1 = sm[(k2+1)*68 + d];
        uint32_t hi, lo;
        split2(f0, f1, hi, lo);
        size_t o = (rowbase + t*128 + k2) / 2;
        ((uint32_t*)dh)[o] = hi;
        ((uint32_t*)dl)[o] = lo;
    }
}

// ---------------------------------------------------------------------------
// gemm_hmma: C[64-row tile][64-col tile] = A(hi/lo) @ B^T(hi/lo), 3-pass split.
// mode 0: A = x image, B = g_Wt (nb 0..23) -> scatter fp32 to g_Q/g_K/g_V
// mode 1: A = O image, B = g_Wot (nb 0..15) -> fp32 out
// block 128 (4 warps x 16 rows); K loop: 16 chunks of 64.
// smem regions (row stride 144B = 36 u32): AH @0, AL @9216, BH @18432, BL @27648
// ---------------------------------------------------------------------------
__global__ void __launch_bounds__(128) gemm_hmma(int mode, float* __restrict__ out)
{
    __shared__ __align__(16) char smem[36864];

    const int tid = threadIdx.x;
    const int wid = tid >> 5;
    const int lane = tid & 31;
    const int g = lane >> 2, tig = lane & 3;

    const int nb = blockIdx.x;
    const int m0 = blockIdx.y * 64;

    const uint4* Ah = (const uint4*)(mode ? g_Oh : g_xh);
    const uint4* Al = (const uint4*)(mode ? g_Ol : g_xl);
    const uint4* Bh = (const uint4*)(mode ? g_Woth : g_Wth);
    const uint4* Bl = (const uint4*)(mode ? g_Wotl : g_Wtl);

    float acc[8][4];
    #pragma unroll
    for (int j = 0; j < 8; j++)
        #pragma unroll
        for (int r = 0; r < 4; r++) acc[j][r] = 0.0f;

    for (int ks = 0; ks < 16; ks++) {
        __syncthreads();
        // ---- load chunk: warp wid fills region wid (512 uint4 each) ----
        {
            char* dst = smem + wid*9216;
            #pragma unroll
            for (int i = 0; i < 16; i++) {
                int idx = lane + 32*i;      // 0..511
                int row = idx >> 3;         // 0..63
                int c   = idx & 7;          // uint4 within 64-elem row chunk
                uint4 v;
                if      (wid == 0) v = Ah[(size_t)(m0 + row)*128 + ks*8 + c];
                else if (wid == 1) v = Al[(size_t)(m0 + row)*128 + ks*8 + c];
                else if (wid == 2) v = Bh[(size_t)(nb*64 + row)*128 + ks*8 + c];
                else               v = Bl[(size_t)(nb*64 + row)*128 + ks*8 + c];
                *(uint4*)(dst + row*144 + c*16) = v;
            }
        }
        __syncthreads();

        const uint32_t* AH_s = (const uint32_t*)smem;             // [m][36]
        const uint32_t* AL_s = (const uint32_t*)(smem + 9216);
        const uint32_t* BH_s = (const uint32_t*)(smem + 18432);   // [n][36]
        const uint32_t* BL_s = (const uint32_t*)(smem + 27648);

        // A fragments for this warp's 16 rows (rows r, r+8), all 4 k-steps
        uint32_t AH[4][4], AL[4][4];
        {
            int r = wid*16 + g;
            #pragma unroll
            for (int kk = 0; kk < 4; kk++) {
                int ai = r*36 + 8*kk + tig;
                AH[kk][0] = AH_s[ai];
                AH[kk][1] = AH_s[ai + 288];   // +8 rows
                AH[kk][2] = AH_s[ai + 4];
                AH[kk][3] = AH_s[ai + 292];
                AL[kk][0] = AL_s[ai];
                AL[kk][1] = AL_s[ai + 288];
                AL[kk][2] = AL_s[ai + 4];
                AL[kk][3] = AL_s[ai + 292];
            }
        }

        #pragma unroll
        for (int j = 0; j < 8; j++) {
            int nrow = (8*j + g) * 36;
            #pragma unroll
            for (int kk = 0; kk < 4; kk++) {
                int bi = nrow + 8*kk + tig;
                uint32_t bh0 = BH_s[bi], bh1 = BH_s[bi + 4];
                uint32_t bl0 = BL_s[bi], bl1 = BL_s[bi + 4];
                mma16816(acc[j], AH[kk], bh0, bh1);
                mma16816(acc[j], AH[kk], bl0, bl1);
                mma16816(acc[j], AL[kk], bh0, bh1);
            }
        }
    }

    // ---- epilogue ----
    int row0 = m0 + wid*16 + g;
    int row1 = row0 + 8;
    #pragma unroll
    for (int j = 0; j < 8; j++) {
        int col = 8*j + 2*tig;
        float2 v0 = make_float2(acc[j][0], acc[j][1]);
        float2 v1 = make_float2(acc[j][2], acc[j][3]);
        if (mode) {
            *(float2*)&out[(size_t)row0*1024 + nb*64 + col] = v0;
            *(float2*)&out[(size_t)row1*1024 + nb*64 + col] = v1;
        } else {
            int b0 = row0 >> 12, tok0 = row0 & 4095;
            int b1 = row1 >> 12, tok1 = row1 & 4095;
            if (nb < 16) {
                *(float2*)&g_Q[(((size_t)b0*HQ_ + nb)*N_ + tok0)*HD_ + col] = v0;
                *(float2*)&g_Q[(((size_t)b1*HQ_ + nb)*N_ + tok1)*HD_ + col] = v1;
            } else if (nb < 20) {
                *(float2*)&g_K[(((size_t)b0*HKV_ + nb-16)*N_ + tok0)*HD_ + col] = v0;
                *(float2*)&g_K[(((size_t)b1*HKV_ + nb-16)*N_ + tok1)*HD_ + col] = v1;
            } else {
                *(float2*)&g_V[(((size_t)b0*HKV_ + nb-20)*N_ + tok0)*HD_ + col] = v0;
                *(float2*)&g_V[(((size_t)b1*HKV_ + nb-20)*N_ + tok1)*HD_ + col] = v1;
            }
        }
    }
}

// ---------------------------------------------------------------------------
// RoPE (in-place, fp32)  [verified]
// ---------------------------------------------------------------------------
__global__ void rope_kernel(int which, int total)
{
    int i = blockIdx.x * blockDim.x + threadIdx.x;
    if (i >= total) return;
    float* buf = which ? g_K : g_Q;
    int d  = i & 31;
    int n  = (i >> 5) & 4095;
    int bh = i >> 17;
    float* p = buf + ((size_t)bh * N_ + n) * HD_;
    float freq = exp2f(-(float)d * (13.287712379549449f / 32.0f));
    float ang = (float)n * freq;
    float s, c;
    sincosf(ang, &s, &c);
    float x1 = p[d];
    float x2 = p[d + 32];
    p[d]      = x1 * c - x2 * s;
    p[d + 32] = x2 * c + x1 * s;
}

// ---------------------------------------------------------------------------
// convert_k: g_K fp32 -> g_Kh/g_Kl  [bkv][key][dim] bf16 hi/lo  [verified]
// ---------------------------------------------------------------------------
__global__ void convert_k()
{
    int bkv = blockIdx.y;
    int key = blockIdx.x * 4 + (threadIdx.x >> 5);
    int lane = threadIdx.x & 31;
    size_t base = ((size_t)bkv * N_ + key) * HD_;
    float2 v = *(const float2*)(g_K + base + lane*2);
    uint32_t hi, lo;
    split2(v.x, v.y, hi, lo);
    ((uint32_t*)g_Kh)[base/2 + lane] = hi;
    ((uint32_t*)g_Kl)[base/2 + lane] = lo;
}

// ---------------------------------------------------------------------------
// convert_vt: g_V fp32 [bkv][key][dim] -> transposed hi/lo [bkv][dim][key]  [verified]
// ---------------------------------------------------------------------------
__global__ void convert_vt()
{
    __shared__ float sm[128*68];
    int bkv = blockIdx.y, t = blockIdx.x, tid = threadIdx.x;
    const float* src = g_V + ((size_t)bkv*N_ + t*128 + tid) * HD_;
    #pragma unroll
    for (int u = 0; u < 16; u++)
        *(float4*)&sm[tid*68 + u*4] = *(const float4*)(src + u*4);
    __syncthreads();
    int d = tid >> 1, half = tid & 1;
    size_t rowbase = ((size_t)bkv*HD_ + d) * N_;
    #pragma unroll
    for (int j = 0; j < 32; j++) {
        int k2 = half*64 + 2*j;
        float f0 = sm[k2*68 + d];
        float f1 = sm[(k2+1)*68 + d];
        uint32_t hi, lo;
        split2(f0, f1, hi, lo);
        size_t o = (rowbase + t*128 + k2) / 2;
        ((uint32_t*)g_Vth)[o] = hi;
        ((uint32_t*)g_Vtl)[o] = lo;
    }
}

// ---------------------------------------------------------------------------
// attn_mma: flash attention on HMMA bf16 hi/lo split.  [verified]
// ---------------------------------------------------------------------------
__global__ void __launch_bounds__(128) attn_mma()
{
    __shared__ __align__(16) char smem[36864];

    const int tid = threadIdx.x;
    const int wid = tid >> 5;
    const int lane = tid & 31;
    const int g = lane >> 2, tig = lane & 3;

    const int qb = blockIdx.x;
    const int bh = blockIdx.y;
    const int b  = bh >> 4;
    const int h  = bh & 15;
    const int bkv = b*HKV_ + (h >> 2);

    uint32_t QH[4][4], QL[4][4];
    {
        const float* Qg = g_Q + (((size_t)(b*HQ_ + h))*N_ + qb*64) * HD_;
        int r0 = wid*16 + g, r1 = r0 + 8;
        #pragma unroll
        for (int kk = 0; kk < 4; kk++) {
            int c0 = 16*kk + 2*tig, c2 = c0 + 8;
            float2 f;
            f = *(const float2*)(Qg + r0*64 + c0);
            split2(f.x*0.125f, f.y*0.125f, QH[kk][0], QL[kk][0]);
            f = *(const float2*)(Qg + r1*64 + c0);
            split2(f.x*0.125f, f.y*0.125f, QH[kk][1], QL[kk][1]);
            f = *(const float2*)(Qg + r0*64 + c2);
            split2(f.x*0.125f, f.y*0.125f, QH[kk][2], QL[kk][2]);
            f = *(const float2*)(Qg + r1*64 + c2);
            split2(f.x*0.125f, f.y*0.125f, QH[kk][3], QL[kk][3]);
        }
    }

    const uint4* Ksh = (const uint4*)g_Kh  + (size_t)bkv*N_*8;
    const uint4* Ksl = (const uint4*)g_Kl  + (size_t)bkv*N_*8;
    const uint4* Vsh = (const uint4*)g_Vth + (size_t)bkv*HD_*512;
    const uint4* Vsl = (const uint4*)g_Vtl + (size_t)bkv*HD_*512;

    float O[8][4];
    #pragma unroll
    for (int j = 0; j < 8; j++)
        #pragma unroll
        for (int r = 0; r < 4; r++) O[j][r] = 0.0f;
    float l0 = 0.0f, l1 = 0.0f;

    for (int t = 0; t < 64; t++) {
        __syncthreads();
        {
            char* dst = smem + wid*9216;
            #pragma unroll
            for (int i = 0; i < 16; i++) {
                int idx = lane + 32*i;
                int row = idx >> 3;
                int c   = idx & 7;
                uint4 v;
                if      (wid == 0) v = Ksh[(size_t)(t*64 + row)*8 + c];
                else if (wid == 1) v = Ksl[(size_t)(t*64 + row)*8 + c];
                else if (wid == 2) v = Vsh[(size_t)row*512 + t*8 + c];
                else               v = Vsl[(size_t)row*512 + t*8 + c];
                *(uint4*)(dst + row*144 + c*16) = v;
            }
        }
        __syncthreads();

        const uint32_t* KH = (const uint32_t*)smem;
        const uint32_t* KL = (const uint32_t*)(smem + 9216);
        const uint32_t* VH = (const uint32_t*)(smem + 18432);
        const uint32_t* VL = (const uint32_t*)(smem + 27648);

        float S[8][4];
        #pragma unroll
        for (int j = 0; j < 8; j++)
            #pragma unroll
            for (int r = 0; r < 4; r++) S[j][r] = 0.0f;

        #pragma unroll
        for (int j = 0; j < 8; j++) {
            int nrow = (8*j + g) * 36;
            #pragma unroll
            for (int kk = 0; kk < 4; kk++) {
                int bi = nrow + 8*kk + tig;
                uint32_t bh0 = KH[bi], bh1 = KH[bi + 4];
                uint32_t bl0 = KL[bi], bl1 = KL[bi + 4];
                mma16816(S[j], QH[kk], bh0, bh1);
                mma16816(S[j], QH[kk], bl0, bl1);
                mma16816(S[j], QL[kk], bh0, bh1);
            }
        }

        #pragma unroll
        for (int j = 0; j < 8; j++) {
            S[j][0] = __expf(S[j][0]);
            S[j][1] = __expf(S[j][1]);
            S[j][2] = __expf(S[j][2]);
            S[j][3] = __expf(S[j][3]);
            l0 += S[j][0] + S[j][1];
            l1 += S[j][2] + S[j][3];
        }

        uint32_t PH[4][4], PL[4][4];
        #pragma unroll
        for (int kk = 0; kk < 4; kk++) {
            int j0 = 2*kk, j1 = 2*kk + 1;
            split2(S[j0][0], S[j0][1], PH[kk][0], PL[kk][0]);
            split2(S[j0][2], S[j0][3], PH[kk][1], PL[kk][1]);
            split2(S[j1][0], S[j1][1], PH[kk][2], PL[kk][2]);
            split2(S[j1][2], S[j1][3], PH[kk][3], PL[kk][3]);
        }

        #pragma unroll
        for (int j = 0; j < 8; j++) {
            int nrow = (8*j + g) * 36;
            #pragma unroll
            for (int kk = 0; kk < 4; kk++) {
                int bi = nrow + 8*kk + tig;
                uint32_t vh0 = VH[bi], vh1 = VH[bi + 4];
                uint32_t vl0 = VL[bi], vl1 = VL[bi + 4];
                mma16816(O[j], PH[kk], vh0, vh1);
                mma16816(O[j], PH[kk], vl0, vl1);
                mma16816(O[j], PL[kk], vh0, vh1);
            }
        }
    }

    l0 += __shfl_xor_sync(0xffffffffu, l0, 1);
    l0 += __shfl_xor_sync(0xffffffffu, l0, 2);
    l1 += __shfl_xor_sync(0xffffffffu, l1, 1);
    l1 += __shfl_xor_sync(0xffffffffu, l1, 2);
    float inv0 = 1.0f / l0, inv1 = 1.0f / l1;

    {
        int tok0 = qb*64 + wid*16 + g;
        float* O0 = g_O + (((size_t)b*N_ + tok0)*HQ_ + h)*HD_;
        float* O1 = O0 + (size_t)8*HQ_*HD_;
        #pragma unroll
        for (int j = 0; j < 8; j++) {
            int col = 8*j + 2*tig;
            *(float2*)(O0 + col) = make_float2(O[j][0]*inv0, O[j][1]*inv0);
            *(float2*)(O1 + col) = make_float2(O[j][2]*inv1, O[j][3]*inv1);
        }
    }
}

// ---------------------------------------------------------------------------
extern "C" void kernel_launch(void* const* d_in, const int* in_sizes, int n_in,
                              void* d_out, int out_size)
{
    const float* x  = (const float*)d_in[0];
    const float* Wq = (const float*)d_in[1];
    const float* Wk = (const float*)d_in[2];
    const float* Wv = (const float*)d_in[3];
    const float* Wo = (const float*)d_in[4];
    float* out = (float*)d_out;

    // 0) operand images for projection GEMMs (globals resolved device-side)
    convert_pairs<<<ROWS_*D_/2/256, 256>>>(x, 0);
    convert_wt<<<dim3(8, 16), 128>>>(Wq, 1024, 0,    0);
    convert_wt<<<dim3(8, 4),  128>>>(Wk, 256,  1024, 0);
    convert_wt<<<dim3(8, 4),  128>>>(Wv, 256,  1280, 0);
    convert_wt<<<dim3(8, 16), 128>>>(Wo, 1024, 0,    1);

    // 1) QKV projections (HMMA) -> fp32 head-major
    gemm_hmma<<<dim3(24, 128), 128>>>(0, nullptr);

    // 2) RoPE on Q and K
    rope_kernel<<<(B_*HQ_*N_*32 + 255)/256, 256>>>(0, B_*HQ_*N_*32);
    rope_kernel<<<(B_*HKV_*N_*32 + 255)/256, 256>>>(1, B_*HKV_*N_*32);

    // 3) K / V^T bf16 hi/lo images
    convert_k<<<dim3(1024, 8), 128>>>();
    convert_vt<<<dim3(32, 8), 128>>>();

    // 4) attention (HMMA) -> g_O fp32
    attn_mma<<<dim3(N_/64, B_*HQ_), 128>>>();

    // 5) O image + output projection (HMMA)
    convert_pairs<<<ROWS_*D_/2/256, 256>>>(nullptr, 1);
    gemm_hmma<<<dim3(16, 128), 128>>>(1, out);
}